// round 15
// baseline (speedup 1.0000x reference)
#include <cuda_runtime.h>

// PureCascadedBitFFN: out[elem, j] = j-th bit (LSB=0) of
// k = ceil(distance[elem] - 0.5) (exact reduction of the 16-step sigmoid
// cascade in the reference: sigmoid(S*x) > 0.5  <=>  x > 0, so the cascade
// collapses to round-half-down + bit extraction).
//
// 128 MB f32 output, never re-read: pinned at the GB300 HBM write wall.
// Steady-state 23.0us (deterministic across R8/R10/R13/R14) = 5.9 TB/s
// total DRAM traffic (~74% of 8 TB/s spec); LSU (29%), ALU (32%), LTS (51%)
// all have headroom -> HBM write drain is the binding wall and the output
// bytes are irreducible.
//
// Falsified alternatives (14 rounds): smem read-dedup (neutral), persistent
// grid (+2us), __stwt write-through (+4us), 16 quads/thread @ grid=1024
// (+1.6us, occupancy loss), cp.async.bulk TMA stores unpipelined (+4.1us)
// and double-buffered pipelined (+4.4us) - TMA bulk writes stall harder
// against the steady-state dirty-L2 victim drain than sector-level STG.
//
// FINAL config: 512-thread blocks, 4096-quad tiles, grid=2048. Each thread:
// 8 quads strided by 512 -> 8 coalesced 2KB block-wide STG.128 bursts;
// front-batched __ldg reads; __stcs evict-first (L2 buffers + burst-forms
// the DRAM drain); bits materialized by integer select of 0x3F800000.

__global__ __launch_bounds__(512) void cascaded_bits_kernel(
    const float* __restrict__ dist,
    float4* __restrict__ out)
{
    const int base = blockIdx.x * 4096 + threadIdx.x;

    float r[8];
    #pragma unroll
    for (int i = 0; i < 8; i++)
        r[i] = __ldg(&dist[(base + i * 512) >> 2]);

    int k[8];
    #pragma unroll
    for (int i = 0; i < 8; i++)
        k[i] = __float2int_ru(r[i] - 0.5f);   // exact round-half-down

    #pragma unroll
    for (int i = 0; i < 8; i++) {
        const int q   = base + i * 512;
        const int bit = (q & 3) << 2;         // starting bit: 0,4,8,12
        float4 v;
        v.x = __int_as_float(((k[i] >> (bit + 0)) & 1) * 0x3F800000);
        v.y = __int_as_float(((k[i] >> (bit + 1)) & 1) * 0x3F800000);
        v.z = __int_as_float(((k[i] >> (bit + 2)) & 1) * 0x3F800000);
        v.w = __int_as_float(((k[i] >> (bit + 3)) & 1) * 0x3F800000);
        __stcs(&out[q], v);                   // streaming: evict-first in L2
    }
}

extern "C" void kernel_launch(void* const* d_in, const int* in_sizes, int n_in,
                              void* d_out, int out_size)
{
    const float* dist = (const float*)d_in[0];
    float4* out = (float4*)d_out;

    int n_elems = in_sizes[0];            // 512*4096 = 2,097,152
    int nquads  = n_elems * 4;            // 8,388,608
    int blocks  = nquads / 4096;          // 2048 (exact)

    cascaded_bits_kernel<<<blocks, 512>>>(dist, out);
}

// round 16
// speedup vs baseline: 1.0556x; 1.0556x over previous
#include <cuda_runtime.h>

// PureCascadedBitFFN: out[elem, j] = j-th bit (LSB=0) of
// k = ceil(distance[elem] - 0.5) (exact reduction of the 16-step sigmoid
// cascade in the reference: sigmoid(S*x) > 0.5  <=>  x > 0, so the cascade
// collapses to round-half-down + bit extraction).
//
// 128 MB f32 output, never re-read: pinned at the GB300 HBM write wall.
// Kernel time 23.0-23.3us across 5 profiled runs = 5.9 TB/s total DRAM
// traffic (~74% of 8 TB/s spec); LSU (29%), ALU (33%), LTS (51%) all have
// headroom -> HBM write drain is the binding wall, output bytes irreducible.
// Bench-level run-to-run noise is +/-1.3us (DVFS/hold state; R14 vs R15
// measured identical source at 22.98 and 24.29us).
//
// Falsified alternatives (15 rounds): smem read-dedup (neutral), persistent
// grid (+2us), __stwt write-through (+4us), 16 quads/thread @ grid=1024
// (+1.6us, occupancy loss), cp.async.bulk TMA stores unpipelined (+4.1us)
// and double-buffered pipelined (+4.4us) - TMA bulk writes stall harder
// against the steady-state dirty-L2 victim drain than sector-level STG.
//
// FINAL config: 512-thread blocks, 4096-quad tiles, grid=2048. Each thread:
// 8 quads strided by 512 -> 8 coalesced 2KB block-wide STG.128 bursts;
// front-batched __ldg reads; __stcs evict-first (L2 buffers + burst-forms
// the DRAM drain); bits materialized by integer select of 0x3F800000.

__global__ __launch_bounds__(512) void cascaded_bits_kernel(
    const float* __restrict__ dist,
    float4* __restrict__ out)
{
    const int base = blockIdx.x * 4096 + threadIdx.x;

    float r[8];
    #pragma unroll
    for (int i = 0; i < 8; i++)
        r[i] = __ldg(&dist[(base + i * 512) >> 2]);

    int k[8];
    #pragma unroll
    for (int i = 0; i < 8; i++)
        k[i] = __float2int_ru(r[i] - 0.5f);   // exact round-half-down

    #pragma unroll
    for (int i = 0; i < 8; i++) {
        const int q   = base + i * 512;
        const int bit = (q & 3) << 2;         // starting bit: 0,4,8,12
        float4 v;
        v.x = __int_as_float(((k[i] >> (bit + 0)) & 1) * 0x3F800000);
        v.y = __int_as_float(((k[i] >> (bit + 1)) & 1) * 0x3F800000);
        v.z = __int_as_float(((k[i] >> (bit + 2)) & 1) * 0x3F800000);
        v.w = __int_as_float(((k[i] >> (bit + 3)) & 1) * 0x3F800000);
        __stcs(&out[q], v);                   // streaming: evict-first in L2
    }
}

extern "C" void kernel_launch(void* const* d_in, const int* in_sizes, int n_in,
                              void* d_out, int out_size)
{
    const float* dist = (const float*)d_in[0];
    float4* out = (float4*)d_out;

    int n_elems = in_sizes[0];            // 512*4096 = 2,097,152
    int nquads  = n_elems * 4;            // 8,388,608
    int blocks  = nquads / 4096;          // 2048 (exact)

    cascaded_bits_kernel<<<blocks, 512>>>(dist, out);
}